// round 12
// baseline (speedup 1.0000x reference)
#include <cuda_runtime.h>
#include <math.h>
#include <float.h>

#define NPTS   1024
#define BATCH  4
#define TOTAL  (BATCH*NPTS)      // 4096
#define DCH    128
#define KMAX   100

// ---------------- scratch (static device globals; no allocation) ----------------
__device__ float4 g_nd[TOTAL*KMAX];          // normalized edge dirs + idx in .w (sorted)
__device__ float  g_raw[6][TOTAL*DCH];       // raw (pre-BN) features per stage
__device__ float  g_fc_m[TOTAL*DCH];
__device__ float  g_fs_m[TOTAL*DCH];
__device__ float  g_fc_g[TOTAL*DCH];
__device__ float  g_fs_g[TOTAL*DCH];
__device__ float  g_scale[6*DCH];
__device__ float  g_shift[6*DCH];

// ---------------- f32x2 helpers -------------------------------------------------
__device__ __forceinline__ unsigned long long pack2(float a, float b) {
    unsigned long long r;
    asm("mov.b64 %0, {%1, %2};" : "=l"(r) : "f"(a), "f"(b));
    return r;
}
__device__ __forceinline__ void unpack2(unsigned long long v, float &a, float &b) {
    asm("mov.b64 {%0, %1}, %2;" : "=f"(a), "=f"(b) : "l"(v));
}
__device__ __forceinline__ void ffma2(unsigned long long &d, unsigned long long a, unsigned long long b) {
    asm("fma.rn.f32x2 %0, %1, %2, %3;" : "=l"(d) : "l"(a), "l"(b), "l"(d));
}

// padded word index for conflict-free 2048-bucket (1024-word) histogram
#define PW(w) ((w) + ((w) >> 5))
#define HWORDS 1056                            // 1024 + 32 pad
#define L2CAP  192                             // level-2 bucket list capacity

// ================= KNN (2 points/block, two-level radix select) + surface convs =
__global__ __launch_bounds__(256) void knn_surf_kernel(
    const float* __restrict__ verts, float4* __restrict__ nd,
    float* __restrict__ raw_l, float* __restrict__ raw_m, float* __restrict__ raw_g,
    const float* __restrict__ dl, const float* __restrict__ dm, const float* __restrict__ dg)
{
    __shared__ float vx[NPTS], vy[NPTS], vz[NPTS];
    __shared__ unsigned int hist[2*HWORDS];           // u16-packed counts
    __shared__ unsigned long long list_s[2][L2CAP];   // tiny level-2 bucket list
    __shared__ unsigned long long sel_s[2][104];
    __shared__ float ndx_s[2][100], ndy_s[2][100], ndz_s[2][100];
    __shared__ float gacc_s[2][4][128];
    __shared__ unsigned int chunk_s[2][128];
    __shared__ unsigned int wtot[2][4];
    __shared__ unsigned int cnt_s[2], selcnt_s[2], B_s[2], q_s[2];
    __shared__ unsigned long long T_s[2];

    int tid = threadIdx.x;
    int pt  = tid >> 7;                 // which of the 2 points
    int st  = tid & 127;                // sub-thread within point
    int p0  = blockIdx.x * 2;
    int b   = p0 >> 10;                 // p0 even -> both points same batch
    int p   = p0 + pt;
    int i   = p & (NPTS-1);
    const float* vb = verts + b*NPTS*3;

    for (int t = tid; t < NPTS; t += 256) {
        vx[t] = vb[3*t+0]; vy[t] = vb[3*t+1]; vz[t] = vb[3*t+2];
    }
    for (int t = tid; t < 2*HWORDS; t += 256) hist[t] = 0;
    if (tid < 2) { cnt_s[tid] = 0; selcnt_s[tid] = 0; }
    __syncthreads();

    float xi = vx[i], yi = vy[i], zi = vz[i];
    float sqi = xi*xi + yi*yi + zi*zi;
    int wb = pt * HWORDS;

    unsigned long long k64[8];
#pragma unroll
    for (int s = 0; s < 8; s++) {
        int j = st + s*128;
        float xj = vx[j], yj = vy[j], zj = vz[j];
        float sqj = xj*xj + yj*yj + zj*zj;
        float dot = xi*xj + yi*yj + zi*zj;
        float d   = sqi + sqj - 2.0f*dot;             // same formula as reference
        unsigned int bits = __float_as_uint(d);
        unsigned int key  = (bits & 0x80000000u) ? ~bits : (bits | 0x80000000u);
        k64[s] = ((unsigned long long)key << 10) | (unsigned)j;
        unsigned int bu = key >> 21;                  // 11-bit level-1 bucket
        atomicAdd(&hist[wb + PW(bu>>1)], (bu & 1u) ? 65536u : 1u);
    }
    __syncthreads();

    int lane = tid & 31;
    int sw = st >> 5;

    // ---- level-1 scan of 2048 bucket counts (16 buckets = 8 words / thread) ----
    {
        unsigned int run = 0;
#pragma unroll
        for (int t = 0; t < 8; t++) {
            unsigned int v = hist[wb + PW(st*8 + t)];
            run += (v & 0xffffu) + (v >> 16);
        }
        chunk_s[pt][st] = run;
    }
    __syncthreads();
    {
        unsigned int xv = chunk_s[pt][st];
        unsigned int inc = xv;
#pragma unroll
        for (int off = 1; off < 32; off <<= 1) {
            unsigned int y = __shfl_up_sync(0xffffffffu, inc, off);
            if (lane >= off) inc += y;
        }
        if (lane == 31) wtot[pt][sw] = inc;
        __syncthreads();
        unsigned int wbase = 0;
        for (int w = 0; w < sw; w++) wbase += wtot[pt][w];
        unsigned int pr = wbase + inc - xv;
#pragma unroll
        for (int t = 0; t < 16; t++) {
            int bu = st*16 + t;
            unsigned int v = hist[wb + PW(bu>>1)];
            unsigned int c = (bu & 1) ? (v >> 16) : (v & 0xffffu);
            if (pr <= 100u && 100u < pr + c) { B_s[pt] = (unsigned)bu; q_s[pt] = 100u - pr; }
            pr += c;
        }
    }
    __syncthreads();

    unsigned int B1 = B_s[pt], q1 = q_s[pt];
    __syncthreads();                     // all reads of B_s/q_s + hist done

    // ---- level-2: histogram of key bits [20:10] within bucket B1 ----
    for (int t = tid; t < 2*HWORDS; t += 256) hist[t] = 0;
    __syncthreads();
#pragma unroll
    for (int s = 0; s < 8; s++) {
        if ((unsigned int)(k64[s] >> 31) == B1) {
            unsigned int bu2 = (unsigned int)(k64[s] >> 20) & 0x7FFu;
            atomicAdd(&hist[wb + PW(bu2>>1)], (bu2 & 1u) ? 65536u : 1u);
        }
    }
    __syncthreads();
    {
        unsigned int run = 0;
#pragma unroll
        for (int t = 0; t < 8; t++) {
            unsigned int v = hist[wb + PW(st*8 + t)];
            run += (v & 0xffffu) + (v >> 16);
        }
        chunk_s[pt][st] = run;
    }
    __syncthreads();
    {
        unsigned int xv = chunk_s[pt][st];
        unsigned int inc = xv;
#pragma unroll
        for (int off = 1; off < 32; off <<= 1) {
            unsigned int y = __shfl_up_sync(0xffffffffu, inc, off);
            if (lane >= off) inc += y;
        }
        if (lane == 31) wtot[pt][sw] = inc;
        __syncthreads();
        unsigned int wbase = 0;
        for (int w = 0; w < sw; w++) wbase += wtot[pt][w];
        unsigned int pr = wbase + inc - xv;
#pragma unroll
        for (int t = 0; t < 16; t++) {
            int bu = st*16 + t;
            unsigned int v = hist[wb + PW(bu>>1)];
            unsigned int c = (bu & 1) ? (v >> 16) : (v & 0xffffu);
            if (pr <= q1 && q1 < pr + c) { B_s[pt] = (unsigned)bu; q_s[pt] = q1 - pr; }
            pr += c;
        }
    }
    __syncthreads();

    unsigned int B2 = B_s[pt], q2 = q_s[pt];
    unsigned int C22 = (B1 << 11) | B2;       // 22-bit refined bucket
    // ---- collect that refined bucket's elements (typically 1-4) ----
#pragma unroll
    for (int s = 0; s < 8; s++) {
        if ((unsigned int)(k64[s] >> 20) == C22) {
            unsigned int idx = atomicAdd(&cnt_s[pt], 1u);
            if (idx < L2CAP) list_s[pt][idx] = k64[s];
        }
    }
    __syncthreads();
    unsigned int cnt = cnt_s[pt]; if (cnt > L2CAP) cnt = L2CAP;
    for (unsigned int ii = st; ii < cnt; ii += 128) {
        unsigned long long me = list_s[pt][ii];
        unsigned int r = 0;
        for (unsigned int j2 = 0; j2 < cnt; j2++) r += (list_s[pt][j2] < me) ? 1u : 0u;
        if (r == q2) T_s[pt] = me;
    }
    __syncthreads();
    unsigned long long T = T_s[pt];

    // ---- compact the 101 smallest (k64 unique -> exactly 101) ----
#pragma unroll
    for (int s = 0; s < 8; s++) {
        if (k64[s] <= T) { unsigned int idx = atomicAdd(&selcnt_s[pt], 1u); sel_s[pt][idx] = k64[s]; }
    }
    __syncthreads();

    // ---- rank the 101, emit sorted nd (rank 0 = self dropped) ----
    if (st < 101) {
        unsigned long long me = sel_s[pt][st];
        unsigned int r = 0;
#pragma unroll 4
        for (int j2 = 0; j2 < 101; j2++) r += (sel_s[pt][j2] < me) ? 1u : 0u;
        if (r > 0) {
            int slot = (int)r - 1;
            int j = (int)(me & 1023u);
            float dx = vx[j]-xi, dy = vy[j]-yi, dz = vz[j]-zi;
            float inv = 1.0f / fmaxf(sqrtf(dx*dx + dy*dy + dz*dz), 1e-12f);
            float nx = dx*inv, ny = dy*inv, nz = dz*inv;
            ndx_s[pt][slot] = nx; ndy_s[pt][slot] = ny; ndz_s[pt][slot] = nz;
            nd[(size_t)p*KMAX + slot] = make_float4(nx, ny, nz, __int_as_float(j));
        }
    }
    __syncthreads();

    // ---- surface convs, rebalanced: g slots w0:[0,10) w1:[10,40) w2:[40,70) w3:[70,100)
    int col0 = lane*4;
    float q0[4], q1a[4], q2a[4];
#pragma unroll
    for (int c = 0; c < 4; c++) {
        int col = col0 + c;
        float a0 = dg[col], a1 = dg[128+col], a2 = dg[256+col];
        float inv = 1.0f / fmaxf(sqrtf(a0*a0+a1*a1+a2*a2), 1e-12f);
        q0[c]=a0*inv; q1a[c]=a1*inv; q2a[c]=a2*inv;
    }
    float accg[4] = {0,0,0,0};

    if (sw == 0) {
        float l0[4], l1[4], l2[4], m0[4], m1[4], m2[4];
#pragma unroll
        for (int c = 0; c < 4; c++) {
            int col = col0 + c;
            float a0, a1, a2, inv;
            a0 = dl[col]; a1 = dl[128+col]; a2 = dl[256+col];
            inv = 1.0f / fmaxf(sqrtf(a0*a0+a1*a1+a2*a2), 1e-12f);
            l0[c]=a0*inv; l1[c]=a1*inv; l2[c]=a2*inv;
            a0 = dm[col]; a1 = dm[128+col]; a2 = dm[256+col];
            inv = 1.0f / fmaxf(sqrtf(a0*a0+a1*a1+a2*a2), 1e-12f);
            m0[c]=a0*inv; m1[c]=a1*inv; m2[c]=a2*inv;
        }
        float accl[4] = {0,0,0,0}, accm[4] = {0,0,0,0};
#pragma unroll 1
        for (int s = 0; s < 20; s++) {
            float nx = ndx_s[pt][s], ny = ndy_s[pt][s], nz = ndz_s[pt][s];
#pragma unroll
            for (int c = 0; c < 4; c++)
                accm[c] = fmaxf(accm[c], nx*m0[c] + ny*m1[c] + nz*m2[c]);
            if (s < 10) {
#pragma unroll
                for (int c = 0; c < 4; c++)
                    accg[c] = fmaxf(accg[c], nx*q0[c] + ny*q1a[c] + nz*q2a[c]);
            }
            if (s < 5) {
#pragma unroll
                for (int c = 0; c < 4; c++)
                    accl[c] = fmaxf(accl[c], nx*l0[c] + ny*l1[c] + nz*l2[c]);
            }
        }
        *(float4*)&raw_l[(size_t)p*DCH + col0] = make_float4(accl[0],accl[1],accl[2],accl[3]);
        *(float4*)&raw_m[(size_t)p*DCH + col0] = make_float4(accm[0],accm[1],accm[2],accm[3]);
    } else {
        int sbeg = (sw == 1) ? 10 : (sw == 2) ? 40 : 70;
#pragma unroll 1
        for (int s = sbeg; s < sbeg + 30; s++) {
            float nx = ndx_s[pt][s], ny = ndy_s[pt][s], nz = ndz_s[pt][s];
#pragma unroll
            for (int c = 0; c < 4; c++)
                accg[c] = fmaxf(accg[c], nx*q0[c] + ny*q1a[c] + nz*q2a[c]);
        }
    }
    *(float4*)&gacc_s[pt][sw][col0] = make_float4(accg[0],accg[1],accg[2],accg[3]);
    __syncthreads();
    float gm = fmaxf(fmaxf(gacc_s[pt][0][st], gacc_s[pt][1][st]),
                     fmaxf(gacc_s[pt][2][st], gacc_s[pt][3][st]));
    raw_g[(size_t)p*DCH + st] = gm;
}

// ================= GEMM core: 16 rows x 256 cols, k-pair f32x2 (R7 config) ======
struct GemmSmem { unsigned long long in_s[16][65]; };

__device__ __forceinline__ void gemm16_body(
    GemmSmem* sm,
    const float* __restrict__ A, const float* __restrict__ sc, const float* __restrict__ sh,
    const float* __restrict__ W, const float* __restrict__ bias,
    float* __restrict__ outc, float* __restrict__ outs, int r0)
{
    int tid = threadIdx.x;
#pragma unroll
    for (int it = 0; it < 8; it++) {
        int idx = tid + it*256;
        int r = idx >> 7, k = idx & 127;
        float x = A[(size_t)(r0+r)*DCH + k];
        float val = fmaxf(fmaf(x, sc[k], sh[k]), 0.f);
        ((float*)&sm->in_s[r][k>>1])[k&1] = val;
    }
    __syncthreads();

    int col0 = (tid & 63) * 4;
    int rg   = tid >> 6;
    const unsigned long long* A0 = sm->in_s[rg*4+0];
    const unsigned long long* A1 = sm->in_s[rg*4+1];
    const unsigned long long* A2 = sm->in_s[rg*4+2];
    const unsigned long long* A3 = sm->in_s[rg*4+3];

    unsigned long long acc[4][4];
#pragma unroll
    for (int c = 0; c < 4; c++)
#pragma unroll
        for (int r = 0; r < 4; r++) acc[c][r] = 0ull;

    float4 wa = *(const float4*)(W + 0*256 + col0);
    float4 wb = *(const float4*)(W + 1*256 + col0);

#pragma unroll 4
    for (int pk = 0; pk < 64; pk++) {
        int np = pk < 63 ? pk + 1 : 63;
        float4 wan = *(const float4*)(W + (2*np+0)*256 + col0);
        float4 wbn = *(const float4*)(W + (2*np+1)*256 + col0);

        unsigned long long w0 = pack2(wa.x, wb.x);
        unsigned long long w1 = pack2(wa.y, wb.y);
        unsigned long long w2 = pack2(wa.z, wb.z);
        unsigned long long w3 = pack2(wa.w, wb.w);
        unsigned long long a0 = A0[pk], a1 = A1[pk], a2 = A2[pk], a3 = A3[pk];

        ffma2(acc[0][0], a0, w0); ffma2(acc[0][1], a1, w0);
        ffma2(acc[0][2], a2, w0); ffma2(acc[0][3], a3, w0);
        ffma2(acc[1][0], a0, w1); ffma2(acc[1][1], a1, w1);
        ffma2(acc[1][2], a2, w1); ffma2(acc[1][3], a3, w1);
        ffma2(acc[2][0], a0, w2); ffma2(acc[2][1], a1, w2);
        ffma2(acc[2][2], a2, w2); ffma2(acc[2][3], a3, w2);
        ffma2(acc[3][0], a0, w3); ffma2(acc[3][1], a1, w3);
        ffma2(acc[3][2], a2, w3); ffma2(acc[3][3], a3, w3);

        wa = wan; wb = wbn;
    }

    float4 bb = *(const float4*)(bias + col0);
    float* dst; int cbase;
    if (col0 >= 128) { dst = outs; cbase = col0 - 128; }
    else             { dst = outc; cbase = col0; }

#pragma unroll
    for (int r = 0; r < 4; r++) {
        float v0, v1, v2, v3, lo, hi;
        unpack2(acc[0][r], lo, hi); v0 = lo + hi + bb.x;
        unpack2(acc[1][r], lo, hi); v1 = lo + hi + bb.y;
        unpack2(acc[2][r], lo, hi); v2 = lo + hi + bb.z;
        unpack2(acc[3][r], lo, hi); v3 = lo + hi + bb.w;
        int row = r0 + rg*4 + r;
        *(float4*)&dst[(size_t)row*DCH + cbase] = make_float4(v0,v1,v2,v3);
    }
}

__global__ __launch_bounds__(256) void gemm_split_kernel(
    const float* A, const float* sc, const float* sh,
    const float* W, const float* bias, float* fc, float* fs)
{
    __shared__ GemmSmem sm;
    gemm16_body(&sm, A, sc, sh, W, bias, fc, fs, blockIdx.x*16);
}

__global__ __launch_bounds__(256) void gemm_dual_kernel(
    const float* A0, const float* sc0, const float* sh0, const float* W0, const float* b0,
    float* fc0, float* fs0,
    const float* A1, const float* sc1, const float* sh1, const float* W1, const float* b1,
    float* fc1, float* fs1)
{
    __shared__ GemmSmem sm;
    int bid = blockIdx.x;
    if (bid < 256) gemm16_body(&sm, A0, sc0, sh0, W0, b0, fc0, fs0, bid*16);
    else           gemm16_body(&sm, A1, sc1, sh1, W1, b1, fc1, fs1, (bid-256)*16);
}

// ---------------- final GEMM: K=384 (3 BN'd sources), relu (R7 config) ----------
__global__ __launch_bounds__(256) void gemm_final_kernel(
    const float* __restrict__ rl, const float* __restrict__ scl, const float* __restrict__ shl,
    const float* __restrict__ rm, const float* __restrict__ scm, const float* __restrict__ shm,
    const float* __restrict__ rg, const float* __restrict__ scg, const float* __restrict__ shg,
    const float* __restrict__ Wd, const float* __restrict__ bd, float* __restrict__ out)
{
    __shared__ unsigned long long in_s[16][193];
    int tid = threadIdx.x;
    int r0 = blockIdx.x * 16;

    const float* srcs[3] = {rl, rm, rg};
    const float* scs[3]  = {scl, scm, scg};
    const float* shs[3]  = {shl, shm, shg};
#pragma unroll
    for (int s = 0; s < 3; s++) {
        const float* A = srcs[s]; const float* sc = scs[s]; const float* sh = shs[s];
#pragma unroll
        for (int it = 0; it < 8; it++) {
            int idx = tid + it*256;
            int r = idx >> 7, k = idx & 127;
            float x = A[(size_t)(r0+r)*DCH + k];
            float val = fmaxf(fmaf(x, sc[k], sh[k]), 0.f);
            ((float*)&in_s[r][64*s + (k>>1)])[k&1] = val;
        }
    }
    __syncthreads();

    int col0 = (tid & 63) * 4;
    int rg_  = tid >> 6;
    const unsigned long long* A0 = in_s[rg_*4+0];
    const unsigned long long* A1 = in_s[rg_*4+1];
    const unsigned long long* A2 = in_s[rg_*4+2];
    const unsigned long long* A3 = in_s[rg_*4+3];

    unsigned long long acc[4][4];
#pragma unroll
    for (int c = 0; c < 4; c++)
#pragma unroll
        for (int r = 0; r < 4; r++) acc[c][r] = 0ull;

    float4 wa = *(const float4*)(Wd + 0*256 + col0);
    float4 wb = *(const float4*)(Wd + 1*256 + col0);

#pragma unroll 4
    for (int pk = 0; pk < 192; pk++) {
        int np = pk < 191 ? pk + 1 : 191;
        float4 wan = *(const float4*)(Wd + (2*np+0)*256 + col0);
        float4 wbn = *(const float4*)(Wd + (2*np+1)*256 + col0);

        unsigned long long w0 = pack2(wa.x, wb.x);
        unsigned long long w1 = pack2(wa.y, wb.y);
        unsigned long long w2 = pack2(wa.z, wb.z);
        unsigned long long w3 = pack2(wa.w, wb.w);
        unsigned long long a0 = A0[pk], a1 = A1[pk], a2 = A2[pk], a3 = A3[pk];

        ffma2(acc[0][0], a0, w0); ffma2(acc[0][1], a1, w0);
        ffma2(acc[0][2], a2, w0); ffma2(acc[0][3], a3, w0);
        ffma2(acc[1][0], a0, w1); ffma2(acc[1][1], a1, w1);
        ffma2(acc[1][2], a2, w1); ffma2(acc[1][3], a3, w1);
        ffma2(acc[2][0], a0, w2); ffma2(acc[2][1], a1, w2);
        ffma2(acc[2][2], a2, w2); ffma2(acc[2][3], a3, w2);
        ffma2(acc[3][0], a0, w3); ffma2(acc[3][1], a1, w3);
        ffma2(acc[3][2], a2, w3); ffma2(acc[3][3], a3, w3);

        wa = wan; wb = wbn;
    }

    float4 bb = *(const float4*)(bd + col0);
#pragma unroll
    for (int r = 0; r < 4; r++) {
        float v0, v1, v2, v3, lo, hi;
        unpack2(acc[0][r], lo, hi); v0 = fmaxf(lo + hi + bb.x, 0.f);
        unpack2(acc[1][r], lo, hi); v1 = fmaxf(lo + hi + bb.y, 0.f);
        unpack2(acc[2][r], lo, hi); v2 = fmaxf(lo + hi + bb.z, 0.f);
        unpack2(acc[3][r], lo, hi); v3 = fmaxf(lo + hi + bb.w, 0.f);
        int row = r0 + rg_*4 + r;
        *(float4*)&out[(size_t)row*256 + col0] = make_float4(v0,v1,v2,v3);
    }
}

// ================= layer conv: warp-pair per point, nd staged in smem ===========
__device__ __forceinline__ void conv_pair_body(
    const float4* __restrict__ nd, const float* __restrict__ dirs,
    const float* __restrict__ fc, const float* __restrict__ fs,
    float* __restrict__ raw, int K, int pbase, float* sacc, float4* ndsh)
{
    int tid = threadIdx.x;

    // stage nd for the block's 4 points (coalesced)
    for (int idx = tid; idx < 4*K; idx += 256) {
        int pp = idx / K;
        int kk = idx - pp*K;
        ndsh[idx] = nd[(size_t)(pbase + pp)*KMAX + kk];
    }

    int lane = tid & 31, warp = tid >> 5;
    int pp = warp >> 1;                 // point within block (0..3)
    int khalf = warp & 1;
    int p = pbase + pp;
    int rowbase = p & ~(NPTS-1);
    int col0 = lane*4;

    float d0[4], d1[4], d2[4];
#pragma unroll
    for (int c = 0; c < 4; c++) {
        int col = col0 + c;
        float a0 = dirs[col], a1 = dirs[128+col], a2 = dirs[256+col];
        float inv = 1.0f / fmaxf(sqrtf(a0*a0+a1*a1+a2*a2), 1e-12f);
        d0[c]=a0*inv; d1[c]=a1*inv; d2[c]=a2*inv;
    }
    __syncthreads();

    float acc[4] = {-FLT_MAX, -FLT_MAX, -FLT_MAX, -FLT_MAX};
    const float4* ndp = ndsh + pp*K;
    int k0 = khalf * (K >> 1);
    int k1 = k0 + (K >> 1);

#pragma unroll 5
    for (int kk = k0; kk < k1; kk++) {
        float4 v = ndp[kk];                        // broadcast LDS.128
        int j = __float_as_int(v.w);
        float4 f = *(const float4*)(fs + (size_t)(rowbase + j)*DCH + col0);
        float t0 = fmaxf(v.x*d0[0] + v.y*d1[0] + v.z*d2[0], 0.0f);
        float t1 = fmaxf(v.x*d0[1] + v.y*d1[1] + v.z*d2[1], 0.0f);
        float t2 = fmaxf(v.x*d0[2] + v.y*d1[2] + v.z*d2[2], 0.0f);
        float t3 = fmaxf(v.x*d0[3] + v.y*d1[3] + v.z*d2[3], 0.0f);
        acc[0] = fmaxf(acc[0], t0*f.x);
        acc[1] = fmaxf(acc[1], t1*f.y);
        acc[2] = fmaxf(acc[2], t2*f.z);
        acc[3] = fmaxf(acc[3], t3*f.w);
    }

    *(float4*)&sacc[warp*128 + col0] = make_float4(acc[0], acc[1], acc[2], acc[3]);
    __syncthreads();

    // combine halves: 4 points x 128 ch = 512 items / 256 thr
#pragma unroll
    for (int it = 0; it < 2; it++) {
        int idx = tid + it*256;
        int qq = idx >> 7;              // point within block
        int c  = idx & 127;
        float vmx = fmaxf(sacc[(2*qq)*128 + c], sacc[(2*qq+1)*128 + c]);
        int pq = pbase + qq;
        raw[(size_t)pq*DCH + c] = fc[(size_t)pq*DCH + c] + vmx;
    }
}

__global__ __launch_bounds__(256) void conv_dual_kernel(
    const float4* nd,
    const float* dirs_m, const float* fc_m, const float* fs_m, float* raw_m,
    const float* dirs_g, const float* fc_g, const float* fs_g, float* raw_g)
{
    __shared__ float sacc[8*128];
    __shared__ float4 ndsh[4*KMAX];
    int bid = blockIdx.x;
    if (bid < 1024) conv_pair_body(nd, dirs_m, fc_m, fs_m, raw_m, 20,  bid*4, sacc, ndsh);
    else            conv_pair_body(nd, dirs_g, fc_g, fs_g, raw_g, 100, (bid-1024)*4, sacc, ndsh);
}

__global__ __launch_bounds__(256) void conv_single_kernel(
    const float4* nd, const float* dirs, const float* fc, const float* fs, float* raw)
{
    __shared__ float sacc[8*128];
    __shared__ float4 ndsh[4*KMAX];
    conv_pair_body(nd, dirs, fc, fs, raw, 100, blockIdx.x*4, sacc, ndsh);
}

// ================= BN stats ======================================================
__device__ __forceinline__ void stats_body(const float* __restrict__ raw,
                                           const float* __restrict__ g,
                                           const float* __restrict__ be,
                                           float* __restrict__ scale,
                                           float* __restrict__ shift, int c4)
{
    int tid = threadIdx.x;
    float s0=0,s1=0,s2=0,s3=0,q0=0,q1=0,q2=0,q3=0;
    for (int r = tid; r < TOTAL; r += 256) {
        float4 v = *(const float4*)(raw + (size_t)r*DCH + c4);
        s0 += v.x; q0 += v.x*v.x;
        s1 += v.y; q1 += v.y*v.y;
        s2 += v.z; q2 += v.z*v.z;
        s3 += v.w; q3 += v.w*v.w;
    }
#pragma unroll
    for (int off = 16; off; off >>= 1) {
        s0 += __shfl_xor_sync(0xffffffffu, s0, off);
        s1 += __shfl_xor_sync(0xffffffffu, s1, off);
        s2 += __shfl_xor_sync(0xffffffffu, s2, off);
        s3 += __shfl_xor_sync(0xffffffffu, s3, off);
        q0 += __shfl_xor_sync(0xffffffffu, q0, off);
        q1 += __shfl_xor_sync(0xffffffffu, q1, off);
        q2 += __shfl_xor_sync(0xffffffffu, q2, off);
        q3 += __shfl_xor_sync(0xffffffffu, q3, off);
    }
    __shared__ float red[8][8];
    int warp = tid >> 5, lane = tid & 31;
    if (lane == 0) {
        red[warp][0]=s0; red[warp][1]=s1; red[warp][2]=s2; red[warp][3]=s3;
        red[warp][4]=q0; red[warp][5]=q1; red[warp][6]=q2; red[warp][7]=q3;
    }
    __syncthreads();
    if (tid < 8) {
        float t = 0.f;
#pragma unroll
        for (int w = 0; w < 8; w++) t += red[w][tid];
        red[0][tid] = t;
    }
    __syncthreads();
    if (tid < 4) {
        float mean = red[0][tid] * (1.0f/TOTAL);
        float var  = fmaxf(red[0][4+tid] * (1.0f/TOTAL) - mean*mean, 0.f);
        float sc   = g[c4+tid] * rsqrtf(var + 1e-5f);
        scale[c4+tid] = sc;
        shift[c4+tid] = be[c4+tid] - mean*sc;
    }
}

__global__ __launch_bounds__(256) void stats1_kernel(const float* raw, const float* g,
                                                     const float* be, float* scale, float* shift)
{
    stats_body(raw, g, be, scale, shift, blockIdx.x*4);
}

__global__ __launch_bounds__(256) void stats2_kernel(
    const float* r0, const float* g0, const float* b0, float* sc0, float* sh0,
    const float* r1, const float* g1, const float* b1, float* sc1, float* sh1)
{
    int stage = blockIdx.x >> 5;
    int c4 = (blockIdx.x & 31) * 4;
    if (stage == 0) stats_body(r0, g0, b0, sc0, sh0, c4);
    else            stats_body(r1, g1, b1, sc1, sh1, c4);
}

__global__ __launch_bounds__(256) void stats3_kernel(
    const float* r0, const float* g0, const float* b0, float* sc0, float* sh0,
    const float* r1, const float* g1, const float* b1, float* sc1, float* sh1,
    const float* r2, const float* g2, const float* b2, float* sc2, float* sh2)
{
    int stage = blockIdx.x >> 5;
    int c4 = (blockIdx.x & 31) * 4;
    if (stage == 0)      stats_body(r0, g0, b0, sc0, sh0, c4);
    else if (stage == 1) stats_body(r1, g1, b1, sc1, sh1, c4);
    else                 stats_body(r2, g2, b2, sc2, sh2, c4);
}

// ================= launcher ======================================================
extern "C" void kernel_launch(void* const* d_in, const int* in_sizes, int n_in,
                              void* d_out, int out_size)
{
    const float* verts   = (const float*)d_in[0];
    const float* dirs_l  = (const float*)d_in[1];
    const float* dirs_m0 = (const float*)d_in[2];
    const float* W_m1    = (const float*)d_in[3];
    const float* b_m1    = (const float*)d_in[4];
    const float* dirs_m1 = (const float*)d_in[5];
    const float* dirs_g0 = (const float*)d_in[6];
    const float* W_g1    = (const float*)d_in[7];
    const float* b_g1    = (const float*)d_in[8];
    const float* dirs_g1 = (const float*)d_in[9];
    const float* W_g2    = (const float*)d_in[10];
    const float* b_g2    = (const float*)d_in[11];
    const float* dirs_g2 = (const float*)d_in[12];
    const float* g_l   = (const float*)d_in[13];
    const float* be_l  = (const float*)d_in[14];
    const float* g_m0  = (const float*)d_in[15];
    const float* be_m0 = (const float*)d_in[16];
    const float* g_m1  = (const float*)d_in[17];
    const float* be_m1 = (const float*)d_in[18];
    const float* g_g0  = (const float*)d_in[19];
    const float* be_g0 = (const float*)d_in[20];
    const float* g_g1  = (const float*)d_in[21];
    const float* be_g1 = (const float*)d_in[22];
    const float* g_g2  = (const float*)d_in[23];
    const float* be_g2 = (const float*)d_in[24];
    const float* W_down = (const float*)d_in[25];
    const float* b_down = (const float*)d_in[26];
    float* out = (float*)d_out;

    float4* nd;    cudaGetSymbolAddress((void**)&nd,    g_nd);
    float*  raw;   cudaGetSymbolAddress((void**)&raw,   g_raw);
    float*  fc_m;  cudaGetSymbolAddress((void**)&fc_m,  g_fc_m);
    float*  fs_m;  cudaGetSymbolAddress((void**)&fs_m,  g_fs_m);
    float*  fc_g;  cudaGetSymbolAddress((void**)&fc_g,  g_fc_g);
    float*  fs_g;  cudaGetSymbolAddress((void**)&fs_g,  g_fs_g);
    float*  scale; cudaGetSymbolAddress((void**)&scale, g_scale);
    float*  shift; cudaGetSymbolAddress((void**)&shift, g_shift);

#define RAW(s) (raw + (size_t)(s)*TOTAL*DCH)
#define SC(s)  (scale + (s)*DCH)
#define SH(s)  (shift + (s)*DCH)

    // 1) KNN (2 points/block, two-level radix) + all three surface convs
    knn_surf_kernel<<<TOTAL/2, 256>>>(verts, nd, RAW(0), RAW(1), RAW(3),
                                      dirs_l, dirs_m0, dirs_g0);
    // 2) BN stats for l, m0, g0
    stats3_kernel<<<96, 256>>>(RAW(0), g_l,  be_l,  SC(0), SH(0),
                               RAW(1), g_m0, be_m0, SC(1), SH(1),
                               RAW(3), g_g0, be_g0, SC(3), SH(3));
    // 3) fm@W for medium and global-1 in one grid
    gemm_dual_kernel<<<512, 256>>>(RAW(1), SC(1), SH(1), W_m1, b_m1, fc_m, fs_m,
                                   RAW(3), SC(3), SH(3), W_g1, b_g1, fc_g, fs_g);
    // 4) layer convs m (K=20) and g1 (K=100), warp-pair per point
    conv_dual_kernel<<<2048, 256>>>(nd, dirs_m1, fc_m, fs_m, RAW(2),
                                        dirs_g1, fc_g, fs_g, RAW(4));
    // 5) BN stats m1 + g1
    stats2_kernel<<<64, 256>>>(RAW(2), g_m1, be_m1, SC(2), SH(2),
                               RAW(4), g_g1, be_g1, SC(4), SH(4));
    // 6) global-2 fm@W
    gemm_split_kernel<<<256, 256>>>(RAW(4), SC(4), SH(4), W_g2, b_g2, fc_g, fs_g);
    // 7) global-2 layer conv (K=100)
    conv_single_kernel<<<1024, 256>>>(nd, dirs_g2, fc_g, fs_g, RAW(5));
    // 8) BN stats g2
    stats1_kernel<<<32, 256>>>(RAW(5), g_g2, be_g2, SC(5), SH(5));
    // 9) concat + down projection + relu
    gemm_final_kernel<<<256, 256>>>(RAW(0), SC(0), SH(0),
                                    RAW(2), SC(2), SH(2),
                                    RAW(5), SC(5), SH(5),
                                    W_down, b_down, out);
#undef RAW
#undef SC
#undef SH
}

// round 14
// speedup vs baseline: 1.0665x; 1.0665x over previous
#include <cuda_runtime.h>
#include <math.h>
#include <float.h>

#define NPTS   1024
#define BATCH  4
#define TOTAL  (BATCH*NPTS)      // 4096
#define DCH    128
#define KMAX   100

// ---------------- scratch (static device globals; no allocation) ----------------
__device__ float4 g_nd[TOTAL*KMAX];          // normalized edge dirs + idx in .w (sorted)
__device__ float  g_raw[6][TOTAL*DCH];       // raw (pre-BN) features per stage
__device__ float  g_fc_m[TOTAL*DCH];
__device__ float  g_fs_m[TOTAL*DCH];
__device__ float  g_fc_g[TOTAL*DCH];
__device__ float  g_fs_g[TOTAL*DCH];
__device__ float  g_scale[6*DCH];
__device__ float  g_shift[6*DCH];

// ---------------- f32x2 helpers -------------------------------------------------
__device__ __forceinline__ unsigned long long pack2(float a, float b) {
    unsigned long long r;
    asm("mov.b64 %0, {%1, %2};" : "=l"(r) : "f"(a), "f"(b));
    return r;
}
__device__ __forceinline__ void unpack2(unsigned long long v, float &a, float &b) {
    asm("mov.b64 {%0, %1}, %2;" : "=f"(a), "=f"(b) : "l"(v));
}
__device__ __forceinline__ void ffma2(unsigned long long &d, unsigned long long a, unsigned long long b) {
    asm("fma.rn.f32x2 %0, %1, %2, %3;" : "=l"(d) : "l"(a), "l"(b), "l"(d));
}

// padded word index for conflict-free 2048-bucket (1024-word) histogram
#define PW(w) ((w) + ((w) >> 5))
#define HWORDS 1056                            // 1024 + 32 pad

// ================= KNN (2 points/block, exact rank select) + surface convs ======
__global__ __launch_bounds__(256) void knn_surf_kernel(
    const float* __restrict__ verts, float4* __restrict__ nd,
    float* __restrict__ raw_l, float* __restrict__ raw_m, float* __restrict__ raw_g,
    const float* __restrict__ dl, const float* __restrict__ dm, const float* __restrict__ dg)
{
    __shared__ float vx[NPTS], vy[NPTS], vz[NPTS];
    __shared__ unsigned int hist[2*HWORDS];           // u16-packed counts
    __shared__ unsigned long long list_s[2][NPTS];
    __shared__ unsigned long long sel_s[2][104];
    __shared__ float ndx_s[2][100], ndy_s[2][100], ndz_s[2][100];
    __shared__ float gacc_s[2][4][128];
    __shared__ unsigned int chunk_s[2][128];
    __shared__ unsigned int wtot[2][4];
    __shared__ unsigned int cnt_s[2], selcnt_s[2], B_s[2], q_s[2];
    __shared__ unsigned long long T_s[2];

    int tid = threadIdx.x;
    int pt  = tid >> 7;                 // which of the 2 points
    int st  = tid & 127;                // sub-thread within point
    int p0  = blockIdx.x * 2;
    int b   = p0 >> 10;                 // p0 even -> both points same batch
    int p   = p0 + pt;
    int i   = p & (NPTS-1);
    const float* vb = verts + b*NPTS*3;

    for (int t = tid; t < NPTS; t += 256) {
        vx[t] = vb[3*t+0]; vy[t] = vb[3*t+1]; vz[t] = vb[3*t+2];
    }
    for (int t = tid; t < 2*HWORDS; t += 256) hist[t] = 0;
    if (tid < 2) { cnt_s[tid] = 0; selcnt_s[tid] = 0; }
    __syncthreads();

    float xi = vx[i], yi = vy[i], zi = vz[i];
    float sqi = xi*xi + yi*yi + zi*zi;
    int wb = pt * HWORDS;

    unsigned long long k64[8];
#pragma unroll
    for (int s = 0; s < 8; s++) {
        int j = st + s*128;
        float xj = vx[j], yj = vy[j], zj = vz[j];
        float sqj = xj*xj + yj*yj + zj*zj;
        float dot = xi*xj + yi*yj + zi*zj;
        float d   = sqi + sqj - 2.0f*dot;             // same formula as reference
        unsigned int bits = __float_as_uint(d);
        unsigned int key  = (bits & 0x80000000u) ? ~bits : (bits | 0x80000000u);
        k64[s] = ((unsigned long long)key << 10) | (unsigned)j;
        unsigned int bu = key >> 21;                  // 11-bit bucket
        atomicAdd(&hist[wb + PW(bu>>1)], (bu & 1u) ? 65536u : 1u);
    }
    __syncthreads();

    // ---- scan of 2048 bucket counts per point (16 buckets = 8 words / thread) ----
    {
        unsigned int run = 0;
#pragma unroll
        for (int t = 0; t < 8; t++) {
            unsigned int v = hist[wb + PW(st*8 + t)];
            run += (v & 0xffffu) + (v >> 16);
        }
        chunk_s[pt][st] = run;
    }
    __syncthreads();

    int lane = tid & 31;
    int sw = st >> 5;
    unsigned int xv = chunk_s[pt][st];
    unsigned int inc = xv;
#pragma unroll
    for (int off = 1; off < 32; off <<= 1) {
        unsigned int y = __shfl_up_sync(0xffffffffu, inc, off);
        if (lane >= off) inc += y;
    }
    if (lane == 31) wtot[pt][sw] = inc;
    __syncthreads();
    unsigned int wbase = 0;
    for (int w = 0; w < sw; w++) wbase += wtot[pt][w];
    unsigned int chunk_base = wbase + inc - xv;

    // ---- locate bucket holding global rank 100 ----
    {
        unsigned int pr = chunk_base;
#pragma unroll
        for (int t = 0; t < 16; t++) {
            int bu = st*16 + t;
            unsigned int v = hist[wb + PW(bu>>1)];
            unsigned int c = (bu & 1) ? (v >> 16) : (v & 0xffffu);
            if (pr <= 100u && 100u < pr + c) { B_s[pt] = (unsigned)bu; q_s[pt] = 100u - pr; }
            pr += c;
        }
    }
    __syncthreads();

    unsigned int B = B_s[pt], q = q_s[pt];
    // ---- collect that bucket's elements ----
#pragma unroll
    for (int s = 0; s < 8; s++) {
        unsigned int bu = (unsigned int)(k64[s] >> 31);       // key>>21
        if (bu == B) { unsigned int idx = atomicAdd(&cnt_s[pt], 1u); list_s[pt][idx] = k64[s]; }
    }
    __syncthreads();
    unsigned int cnt = cnt_s[pt];
    for (unsigned int ii = st; ii < cnt; ii += 128) {
        unsigned long long me = list_s[pt][ii];
        unsigned int r = 0;
        for (unsigned int j2 = 0; j2 < cnt; j2++) r += (list_s[pt][j2] < me) ? 1u : 0u;
        if (r == q) T_s[pt] = me;
    }
    __syncthreads();
    unsigned long long T = T_s[pt];

    // ---- compact the 101 smallest (keys unique -> exactly 101) ----
#pragma unroll
    for (int s = 0; s < 8; s++) {
        if (k64[s] <= T) { unsigned int idx = atomicAdd(&selcnt_s[pt], 1u); sel_s[pt][idx] = k64[s]; }
    }
    __syncthreads();

    // ---- rank the 101, emit sorted nd (rank 0 = self dropped) ----
    if (st < 101) {
        unsigned long long me = sel_s[pt][st];
        unsigned int r = 0;
#pragma unroll 4
        for (int j2 = 0; j2 < 101; j2++) r += (sel_s[pt][j2] < me) ? 1u : 0u;
        if (r > 0) {
            int slot = (int)r - 1;
            int j = (int)(me & 1023u);
            float dx = vx[j]-xi, dy = vy[j]-yi, dz = vz[j]-zi;
            float inv = 1.0f / fmaxf(sqrtf(dx*dx + dy*dy + dz*dz), 1e-12f);
            float nx = dx*inv, ny = dy*inv, nz = dz*inv;
            ndx_s[pt][slot] = nx; ndy_s[pt][slot] = ny; ndz_s[pt][slot] = nz;
            nd[(size_t)p*KMAX + slot] = make_float4(nx, ny, nz, __int_as_float(j));
        }
    }
    __syncthreads();

    // ---- surface convs, rebalanced: g slots w0:[0,10) w1:[10,40) w2:[40,70) w3:[70,100)
    int col0 = lane*4;
    float q0[4], q1a[4], q2a[4];
#pragma unroll
    for (int c = 0; c < 4; c++) {
        int col = col0 + c;
        float a0 = dg[col], a1 = dg[128+col], a2 = dg[256+col];
        float inv = 1.0f / fmaxf(sqrtf(a0*a0+a1*a1+a2*a2), 1e-12f);
        q0[c]=a0*inv; q1a[c]=a1*inv; q2a[c]=a2*inv;
    }
    float accg[4] = {0,0,0,0};

    if (sw == 0) {
        float l0[4], l1[4], l2[4], m0[4], m1[4], m2[4];
#pragma unroll
        for (int c = 0; c < 4; c++) {
            int col = col0 + c;
            float a0, a1, a2, inv;
            a0 = dl[col]; a1 = dl[128+col]; a2 = dl[256+col];
            inv = 1.0f / fmaxf(sqrtf(a0*a0+a1*a1+a2*a2), 1e-12f);
            l0[c]=a0*inv; l1[c]=a1*inv; l2[c]=a2*inv;
            a0 = dm[col]; a1 = dm[128+col]; a2 = dm[256+col];
            inv = 1.0f / fmaxf(sqrtf(a0*a0+a1*a1+a2*a2), 1e-12f);
            m0[c]=a0*inv; m1[c]=a1*inv; m2[c]=a2*inv;
        }
        float accl[4] = {0,0,0,0}, accm[4] = {0,0,0,0};
#pragma unroll 1
        for (int s = 0; s < 20; s++) {
            float nx = ndx_s[pt][s], ny = ndy_s[pt][s], nz = ndz_s[pt][s];
#pragma unroll
            for (int c = 0; c < 4; c++)
                accm[c] = fmaxf(accm[c], nx*m0[c] + ny*m1[c] + nz*m2[c]);
            if (s < 10) {
#pragma unroll
                for (int c = 0; c < 4; c++)
                    accg[c] = fmaxf(accg[c], nx*q0[c] + ny*q1a[c] + nz*q2a[c]);
            }
            if (s < 5) {
#pragma unroll
                for (int c = 0; c < 4; c++)
                    accl[c] = fmaxf(accl[c], nx*l0[c] + ny*l1[c] + nz*l2[c]);
            }
        }
        *(float4*)&raw_l[(size_t)p*DCH + col0] = make_float4(accl[0],accl[1],accl[2],accl[3]);
        *(float4*)&raw_m[(size_t)p*DCH + col0] = make_float4(accm[0],accm[1],accm[2],accm[3]);
    } else {
        int sbeg = (sw == 1) ? 10 : (sw == 2) ? 40 : 70;
#pragma unroll 1
        for (int s = sbeg; s < sbeg + 30; s++) {
            float nx = ndx_s[pt][s], ny = ndy_s[pt][s], nz = ndz_s[pt][s];
#pragma unroll
            for (int c = 0; c < 4; c++)
                accg[c] = fmaxf(accg[c], nx*q0[c] + ny*q1a[c] + nz*q2a[c]);
        }
    }
    *(float4*)&gacc_s[pt][sw][col0] = make_float4(accg[0],accg[1],accg[2],accg[3]);
    __syncthreads();
    float gm = fmaxf(fmaxf(gacc_s[pt][0][st], gacc_s[pt][1][st]),
                     fmaxf(gacc_s[pt][2][st], gacc_s[pt][3][st]));
    raw_g[(size_t)p*DCH + st] = gm;
}

// ================= GEMM core: 16 rows x 256 cols, k-pair f32x2 (R7 config) ======
struct GemmSmem { unsigned long long in_s[16][65]; };

__device__ __forceinline__ void gemm16_body(
    GemmSmem* sm,
    const float* __restrict__ A, const float* __restrict__ sc, const float* __restrict__ sh,
    const float* __restrict__ W, const float* __restrict__ bias,
    float* __restrict__ outc, float* __restrict__ outs, int r0)
{
    int tid = threadIdx.x;
#pragma unroll
    for (int it = 0; it < 8; it++) {
        int idx = tid + it*256;
        int r = idx >> 7, k = idx & 127;
        float x = A[(size_t)(r0+r)*DCH + k];
        float val = fmaxf(fmaf(x, sc[k], sh[k]), 0.f);
        ((float*)&sm->in_s[r][k>>1])[k&1] = val;
    }
    __syncthreads();

    int col0 = (tid & 63) * 4;
    int rg   = tid >> 6;
    const unsigned long long* A0 = sm->in_s[rg*4+0];
    const unsigned long long* A1 = sm->in_s[rg*4+1];
    const unsigned long long* A2 = sm->in_s[rg*4+2];
    const unsigned long long* A3 = sm->in_s[rg*4+3];

    unsigned long long acc[4][4];
#pragma unroll
    for (int c = 0; c < 4; c++)
#pragma unroll
        for (int r = 0; r < 4; r++) acc[c][r] = 0ull;

    float4 wa = *(const float4*)(W + 0*256 + col0);
    float4 wb = *(const float4*)(W + 1*256 + col0);

#pragma unroll 4
    for (int pk = 0; pk < 64; pk++) {
        int np = pk < 63 ? pk + 1 : 63;
        float4 wan = *(const float4*)(W + (2*np+0)*256 + col0);
        float4 wbn = *(const float4*)(W + (2*np+1)*256 + col0);

        unsigned long long w0 = pack2(wa.x, wb.x);
        unsigned long long w1 = pack2(wa.y, wb.y);
        unsigned long long w2 = pack2(wa.z, wb.z);
        unsigned long long w3 = pack2(wa.w, wb.w);
        unsigned long long a0 = A0[pk], a1 = A1[pk], a2 = A2[pk], a3 = A3[pk];

        ffma2(acc[0][0], a0, w0); ffma2(acc[0][1], a1, w0);
        ffma2(acc[0][2], a2, w0); ffma2(acc[0][3], a3, w0);
        ffma2(acc[1][0], a0, w1); ffma2(acc[1][1], a1, w1);
        ffma2(acc[1][2], a2, w1); ffma2(acc[1][3], a3, w1);
        ffma2(acc[2][0], a0, w2); ffma2(acc[2][1], a1, w2);
        ffma2(acc[2][2], a2, w2); ffma2(acc[2][3], a3, w2);
        ffma2(acc[3][0], a0, w3); ffma2(acc[3][1], a1, w3);
        ffma2(acc[3][2], a2, w3); ffma2(acc[3][3], a3, w3);

        wa = wan; wb = wbn;
    }

    float4 bb = *(const float4*)(bias + col0);
    float* dst; int cbase;
    if (col0 >= 128) { dst = outs; cbase = col0 - 128; }
    else             { dst = outc; cbase = col0; }

#pragma unroll
    for (int r = 0; r < 4; r++) {
        float v0, v1, v2, v3, lo, hi;
        unpack2(acc[0][r], lo, hi); v0 = lo + hi + bb.x;
        unpack2(acc[1][r], lo, hi); v1 = lo + hi + bb.y;
        unpack2(acc[2][r], lo, hi); v2 = lo + hi + bb.z;
        unpack2(acc[3][r], lo, hi); v3 = lo + hi + bb.w;
        int row = r0 + rg*4 + r;
        *(float4*)&dst[(size_t)row*DCH + cbase] = make_float4(v0,v1,v2,v3);
    }
}

__global__ __launch_bounds__(256) void gemm_split_kernel(
    const float* A, const float* sc, const float* sh,
    const float* W, const float* bias, float* fc, float* fs)
{
    __shared__ GemmSmem sm;
    gemm16_body(&sm, A, sc, sh, W, bias, fc, fs, blockIdx.x*16);
}

__global__ __launch_bounds__(256) void gemm_dual_kernel(
    const float* A0, const float* sc0, const float* sh0, const float* W0, const float* b0,
    float* fc0, float* fs0,
    const float* A1, const float* sc1, const float* sh1, const float* W1, const float* b1,
    float* fc1, float* fs1)
{
    __shared__ GemmSmem sm;
    int bid = blockIdx.x;
    if (bid < 256) gemm16_body(&sm, A0, sc0, sh0, W0, b0, fc0, fs0, bid*16);
    else           gemm16_body(&sm, A1, sc1, sh1, W1, b1, fc1, fs1, (bid-256)*16);
}

// ---------------- final GEMM: K=384 (3 BN'd sources), relu (R7 config) ----------
__global__ __launch_bounds__(256) void gemm_final_kernel(
    const float* __restrict__ rl, const float* __restrict__ scl, const float* __restrict__ shl,
    const float* __restrict__ rm, const float* __restrict__ scm, const float* __restrict__ shm,
    const float* __restrict__ rg, const float* __restrict__ scg, const float* __restrict__ shg,
    const float* __restrict__ Wd, const float* __restrict__ bd, float* __restrict__ out)
{
    __shared__ unsigned long long in_s[16][193];
    int tid = threadIdx.x;
    int r0 = blockIdx.x * 16;

    const float* srcs[3] = {rl, rm, rg};
    const float* scs[3]  = {scl, scm, scg};
    const float* shs[3]  = {shl, shm, shg};
#pragma unroll
    for (int s = 0; s < 3; s++) {
        const float* A = srcs[s]; const float* sc = scs[s]; const float* sh = shs[s];
#pragma unroll
        for (int it = 0; it < 8; it++) {
            int idx = tid + it*256;
            int r = idx >> 7, k = idx & 127;
            float x = A[(size_t)(r0+r)*DCH + k];
            float val = fmaxf(fmaf(x, sc[k], sh[k]), 0.f);
            ((float*)&in_s[r][64*s + (k>>1)])[k&1] = val;
        }
    }
    __syncthreads();

    int col0 = (tid & 63) * 4;
    int rg_  = tid >> 6;
    const unsigned long long* A0 = in_s[rg_*4+0];
    const unsigned long long* A1 = in_s[rg_*4+1];
    const unsigned long long* A2 = in_s[rg_*4+2];
    const unsigned long long* A3 = in_s[rg_*4+3];

    unsigned long long acc[4][4];
#pragma unroll
    for (int c = 0; c < 4; c++)
#pragma unroll
        for (int r = 0; r < 4; r++) acc[c][r] = 0ull;

    float4 wa = *(const float4*)(Wd + 0*256 + col0);
    float4 wb = *(const float4*)(Wd + 1*256 + col0);

#pragma unroll 4
    for (int pk = 0; pk < 192; pk++) {
        int np = pk < 191 ? pk + 1 : 191;
        float4 wan = *(const float4*)(Wd + (2*np+0)*256 + col0);
        float4 wbn = *(const float4*)(Wd + (2*np+1)*256 + col0);

        unsigned long long w0 = pack2(wa.x, wb.x);
        unsigned long long w1 = pack2(wa.y, wb.y);
        unsigned long long w2 = pack2(wa.z, wb.z);
        unsigned long long w3 = pack2(wa.w, wb.w);
        unsigned long long a0 = A0[pk], a1 = A1[pk], a2 = A2[pk], a3 = A3[pk];

        ffma2(acc[0][0], a0, w0); ffma2(acc[0][1], a1, w0);
        ffma2(acc[0][2], a2, w0); ffma2(acc[0][3], a3, w0);
        ffma2(acc[1][0], a0, w1); ffma2(acc[1][1], a1, w1);
        ffma2(acc[1][2], a2, w1); ffma2(acc[1][3], a3, w1);
        ffma2(acc[2][0], a0, w2); ffma2(acc[2][1], a1, w2);
        ffma2(acc[2][2], a2, w2); ffma2(acc[2][3], a3, w2);
        ffma2(acc[3][0], a0, w3); ffma2(acc[3][1], a1, w3);
        ffma2(acc[3][2], a2, w3); ffma2(acc[3][3], a3, w3);

        wa = wan; wb = wbn;
    }

    float4 bb = *(const float4*)(bd + col0);
#pragma unroll
    for (int r = 0; r < 4; r++) {
        float v0, v1, v2, v3, lo, hi;
        unpack2(acc[0][r], lo, hi); v0 = fmaxf(lo + hi + bb.x, 0.f);
        unpack2(acc[1][r], lo, hi); v1 = fmaxf(lo + hi + bb.y, 0.f);
        unpack2(acc[2][r], lo, hi); v2 = fmaxf(lo + hi + bb.z, 0.f);
        unpack2(acc[3][r], lo, hi); v3 = fmaxf(lo + hi + bb.w, 0.f);
        int row = r0 + rg_*4 + r;
        *(float4*)&out[(size_t)row*256 + col0] = make_float4(v0,v1,v2,v3);
    }
}

// ================= layer conv: warp-pair per point, nd staged in smem ===========
__device__ __forceinline__ void conv_pair_body(
    const float4* __restrict__ nd, const float* __restrict__ dirs,
    const float* __restrict__ fc, const float* __restrict__ fs,
    float* __restrict__ raw, int K, int pbase, float* sacc, float4* ndsh)
{
    int tid = threadIdx.x;

    // stage nd for the block's 4 points (coalesced)
    for (int idx = tid; idx < 4*K; idx += 256) {
        int pp = idx / K;
        int kk = idx - pp*K;
        ndsh[idx] = nd[(size_t)(pbase + pp)*KMAX + kk];
    }

    int lane = tid & 31, warp = tid >> 5;
    int pp = warp >> 1;                 // point within block (0..3)
    int khalf = warp & 1;
    int p = pbase + pp;
    int rowbase = p & ~(NPTS-1);
    int col0 = lane*4;

    float d0[4], d1[4], d2[4];
#pragma unroll
    for (int c = 0; c < 4; c++) {
        int col = col0 + c;
        float a0 = dirs[col], a1 = dirs[128+col], a2 = dirs[256+col];
        float inv = 1.0f / fmaxf(sqrtf(a0*a0+a1*a1+a2*a2), 1e-12f);
        d0[c]=a0*inv; d1[c]=a1*inv; d2[c]=a2*inv;
    }
    __syncthreads();

    float acc[4] = {-FLT_MAX, -FLT_MAX, -FLT_MAX, -FLT_MAX};
    const float4* ndp = ndsh + pp*K;
    int k0 = khalf * (K >> 1);
    int k1 = k0 + (K >> 1);

#pragma unroll 5
    for (int kk = k0; kk < k1; kk++) {
        float4 v = ndp[kk];                        // broadcast LDS.128
        int j = __float_as_int(v.w);
        float4 f = *(const float4*)(fs + (size_t)(rowbase + j)*DCH + col0);
        float t0 = fmaxf(v.x*d0[0] + v.y*d1[0] + v.z*d2[0], 0.0f);
        float t1 = fmaxf(v.x*d0[1] + v.y*d1[1] + v.z*d2[1], 0.0f);
        float t2 = fmaxf(v.x*d0[2] + v.y*d1[2] + v.z*d2[2], 0.0f);
        float t3 = fmaxf(v.x*d0[3] + v.y*d1[3] + v.z*d2[3], 0.0f);
        acc[0] = fmaxf(acc[0], t0*f.x);
        acc[1] = fmaxf(acc[1], t1*f.y);
        acc[2] = fmaxf(acc[2], t2*f.z);
        acc[3] = fmaxf(acc[3], t3*f.w);
    }

    *(float4*)&sacc[warp*128 + col0] = make_float4(acc[0], acc[1], acc[2], acc[3]);
    __syncthreads();

    // combine halves: 4 points x 128 ch = 512 items / 256 thr
#pragma unroll
    for (int it = 0; it < 2; it++) {
        int idx = tid + it*256;
        int qq = idx >> 7;              // point within block
        int c  = idx & 127;
        float vmx = fmaxf(sacc[(2*qq)*128 + c], sacc[(2*qq+1)*128 + c]);
        int pq = pbase + qq;
        raw[(size_t)pq*DCH + c] = fc[(size_t)pq*DCH + c] + vmx;
    }
}

__global__ __launch_bounds__(256) void conv_dual_kernel(
    const float4* nd,
    const float* dirs_m, const float* fc_m, const float* fs_m, float* raw_m,
    const float* dirs_g, const float* fc_g, const float* fs_g, float* raw_g)
{
    __shared__ float sacc[8*128];
    __shared__ float4 ndsh[4*KMAX];
    int bid = blockIdx.x;
    if (bid < 1024) conv_pair_body(nd, dirs_m, fc_m, fs_m, raw_m, 20,  bid*4, sacc, ndsh);
    else            conv_pair_body(nd, dirs_g, fc_g, fs_g, raw_g, 100, (bid-1024)*4, sacc, ndsh);
}

__global__ __launch_bounds__(256) void conv_single_kernel(
    const float4* nd, const float* dirs, const float* fc, const float* fs, float* raw)
{
    __shared__ float sacc[8*128];
    __shared__ float4 ndsh[4*KMAX];
    conv_pair_body(nd, dirs, fc, fs, raw, 100, blockIdx.x*4, sacc, ndsh);
}

// ================= BN stats ======================================================
__device__ __forceinline__ void stats_body(const float* __restrict__ raw,
                                           const float* __restrict__ g,
                                           const float* __restrict__ be,
                                           float* __restrict__ scale,
                                           float* __restrict__ shift, int c4)
{
    int tid = threadIdx.x;
    float s0=0,s1=0,s2=0,s3=0,q0=0,q1=0,q2=0,q3=0;
    for (int r = tid; r < TOTAL; r += 256) {
        float4 v = *(const float4*)(raw + (size_t)r*DCH + c4);
        s0 += v.x; q0 += v.x*v.x;
        s1 += v.y; q1 += v.y*v.y;
        s2 += v.z; q2 += v.z*v.z;
        s3 += v.w; q3 += v.w*v.w;
    }
#pragma unroll
    for (int off = 16; off; off >>= 1) {
        s0 += __shfl_xor_sync(0xffffffffu, s0, off);
        s1 += __shfl_xor_sync(0xffffffffu, s1, off);
        s2 += __shfl_xor_sync(0xffffffffu, s2, off);
        s3 += __shfl_xor_sync(0xffffffffu, s3, off);
        q0 += __shfl_xor_sync(0xffffffffu, q0, off);
        q1 += __shfl_xor_sync(0xffffffffu, q1, off);
        q2 += __shfl_xor_sync(0xffffffffu, q2, off);
        q3 += __shfl_xor_sync(0xffffffffu, q3, off);
    }
    __shared__ float red[8][8];
    int warp = tid >> 5, lane = tid & 31;
    if (lane == 0) {
        red[warp][0]=s0; red[warp][1]=s1; red[warp][2]=s2; red[warp][3]=s3;
        red[warp][4]=q0; red[warp][5]=q1; red[warp][6]=q2; red[warp][7]=q3;
    }
    __syncthreads();
    if (tid < 8) {
        float t = 0.f;
#pragma unroll
        for (int w = 0; w < 8; w++) t += red[w][tid];
        red[0][tid] = t;
    }
    __syncthreads();
    if (tid < 4) {
        float mean = red[0][tid] * (1.0f/TOTAL);
        float var  = fmaxf(red[0][4+tid] * (1.0f/TOTAL) - mean*mean, 0.f);
        float sc   = g[c4+tid] * rsqrtf(var + 1e-5f);
        scale[c4+tid] = sc;
        shift[c4+tid] = be[c4+tid] - mean*sc;
    }
}

__global__ __launch_bounds__(256) void stats1_kernel(const float* raw, const float* g,
                                                     const float* be, float* scale, float* shift)
{
    stats_body(raw, g, be, scale, shift, blockIdx.x*4);
}

__global__ __launch_bounds__(256) void stats2_kernel(
    const float* r0, const float* g0, const float* b0, float* sc0, float* sh0,
    const float* r1, const float* g1, const float* b1, float* sc1, float* sh1)
{
    int stage = blockIdx.x >> 5;
    int c4 = (blockIdx.x & 31) * 4;
    if (stage == 0) stats_body(r0, g0, b0, sc0, sh0, c4);
    else            stats_body(r1, g1, b1, sc1, sh1, c4);
}

__global__ __launch_bounds__(256) void stats3_kernel(
    const float* r0, const float* g0, const float* b0, float* sc0, float* sh0,
    const float* r1, const float* g1, const float* b1, float* sc1, float* sh1,
    const float* r2, const float* g2, const float* b2, float* sc2, float* sh2)
{
    int stage = blockIdx.x >> 5;
    int c4 = (blockIdx.x & 31) * 4;
    if (stage == 0)      stats_body(r0, g0, b0, sc0, sh0, c4);
    else if (stage == 1) stats_body(r1, g1, b1, sc1, sh1, c4);
    else                 stats_body(r2, g2, b2, sc2, sh2, c4);
}

// ================= launcher ======================================================
extern "C" void kernel_launch(void* const* d_in, const int* in_sizes, int n_in,
                              void* d_out, int out_size)
{
    const float* verts   = (const float*)d_in[0];
    const float* dirs_l  = (const float*)d_in[1];
    const float* dirs_m0 = (const float*)d_in[2];
    const float* W_m1    = (const float*)d_in[3];
    const float* b_m1    = (const float*)d_in[4];
    const float* dirs_m1 = (const float*)d_in[5];
    const float* dirs_g0 = (const float*)d_in[6];
    const float* W_g1    = (const float*)d_in[7];
    const float* b_g1    = (const float*)d_in[8];
    const float* dirs_g1 = (const float*)d_in[9];
    const float* W_g2    = (const float*)d_in[10];
    const float* b_g2    = (const float*)d_in[11];
    const float* dirs_g2 = (const float*)d_in[12];
    const float* g_l   = (const float*)d_in[13];
    const float* be_l  = (const float*)d_in[14];
    const float* g_m0  = (const float*)d_in[15];
    const float* be_m0 = (const float*)d_in[16];
    const float* g_m1  = (const float*)d_in[17];
    const float* be_m1 = (const float*)d_in[18];
    const float* g_g0  = (const float*)d_in[19];
    const float* be_g0 = (const float*)d_in[20];
    const float* g_g1  = (const float*)d_in[21];
    const float* be_g1 = (const float*)d_in[22];
    const float* g_g2  = (const float*)d_in[23];
    const float* be_g2 = (const float*)d_in[24];
    const float* W_down = (const float*)d_in[25];
    const float* b_down = (const float*)d_in[26];
    float* out = (float*)d_out;

    float4* nd;    cudaGetSymbolAddress((void**)&nd,    g_nd);
    float*  raw;   cudaGetSymbolAddress((void**)&raw,   g_raw);
    float*  fc_m;  cudaGetSymbolAddress((void**)&fc_m,  g_fc_m);
    float*  fs_m;  cudaGetSymbolAddress((void**)&fs_m,  g_fs_m);
    float*  fc_g;  cudaGetSymbolAddress((void**)&fc_g,  g_fc_g);
    float*  fs_g;  cudaGetSymbolAddress((void**)&fs_g,  g_fs_g);
    float*  scale; cudaGetSymbolAddress((void**)&scale, g_scale);
    float*  shift; cudaGetSymbolAddress((void**)&shift, g_shift);

#define RAW(s) (raw + (size_t)(s)*TOTAL*DCH)
#define SC(s)  (scale + (s)*DCH)
#define SH(s)  (shift + (s)*DCH)

    // 1) KNN (2 points/block, single-level rank select) + all three surface convs
    knn_surf_kernel<<<TOTAL/2, 256>>>(verts, nd, RAW(0), RAW(1), RAW(3),
                                      dirs_l, dirs_m0, dirs_g0);
    // 2) BN stats for l, m0, g0
    stats3_kernel<<<96, 256>>>(RAW(0), g_l,  be_l,  SC(0), SH(0),
                               RAW(1), g_m0, be_m0, SC(1), SH(1),
                               RAW(3), g_g0, be_g0, SC(3), SH(3));
    // 3) fm@W for medium and global-1 in one grid
    gemm_dual_kernel<<<512, 256>>>(RAW(1), SC(1), SH(1), W_m1, b_m1, fc_m, fs_m,
                                   RAW(3), SC(3), SH(3), W_g1, b_g1, fc_g, fs_g);
    // 4) layer convs m (K=20) and g1 (K=100), warp-pair per point, nd staged
    conv_dual_kernel<<<2048, 256>>>(nd, dirs_m1, fc_m, fs_m, RAW(2),
                                        dirs_g1, fc_g, fs_g, RAW(4));
    // 5) BN stats m1 + g1
    stats2_kernel<<<64, 256>>>(RAW(2), g_m1, be_m1, SC(2), SH(2),
                               RAW(4), g_g1, be_g1, SC(4), SH(4));
    // 6) global-2 fm@W
    gemm_split_kernel<<<256, 256>>>(RAW(4), SC(4), SH(4), W_g2, b_g2, fc_g, fs_g);
    // 7) global-2 layer conv (K=100)
    conv_single_kernel<<<1024, 256>>>(nd, dirs_g2, fc_g, fs_g, RAW(5));
    // 8) BN stats g2
    stats1_kernel<<<32, 256>>>(RAW(5), g_g2, be_g2, SC(5), SH(5));
    // 9) concat + down projection + relu
    gemm_final_kernel<<<256, 256>>>(RAW(0), SC(0), SH(0),
                                    RAW(2), SC(2), SH(2),
                                    RAW(5), SC(5), SH(5),
                                    W_down, b_down, out);
#undef RAW
#undef SC
#undef SH
}